// round 1
// baseline (speedup 1.0000x reference)
#include <cuda_runtime.h>
#include <math.h>

#define NN      100000
#define DD      64
#define E_INTRA 1200000
#define E_INTER 400000
#define E_TOT   (E_INTRA + E_INTER + NN)   // 1,700,000 (self loops appended)
#define NGR     256
#define GAT_SLOPE 0.2f
#define FC_SLOPE  0.01f

// ---------------- static scratch (no allocations allowed) ----------------
__device__ float g_bufA[NN * DD];
__device__ float g_bufB[NN * DD];   // h2 = hin @ W^T
__device__ float g_bufC[NN * DD];
__device__ float g_e[E_TOT];
__device__ float g_as[NN];
__device__ float g_ad[NN];
__device__ float g_emax[NN];
__device__ float g_denom[NN];
__device__ float g_pool[NGR * DD];

// ---------------- helpers ----------------
__device__ __forceinline__ void edge_sd(int t, const int* __restrict__ ei_a,
                                        const int* __restrict__ ei_b, int& s, int& d) {
    if (t < E_INTRA) {
        s = ei_a[t];
        d = ei_a[E_INTRA + t];
    } else if (t < E_INTRA + E_INTER) {
        int u = t - E_INTRA;
        s = ei_b[u];
        d = ei_b[E_INTER + u];
    } else {
        s = d = t - (E_INTRA + E_INTER);
    }
}

__device__ __forceinline__ void atomicMaxF(float* addr, float v) {
    int old = __float_as_int(*addr);
    while (__int_as_float(old) < v) {
        int assumed = old;
        old = atomicCAS((int*)addr, assumed, __float_as_int(v));
        if (old == assumed) break;
    }
}

// ---------------- GEMM: out = act(in @ W^T [+ bias]) ----------------
// in [NN,64], W [64,64] row-major (out[i][c] = sum_k in[i][k]*W[c][k])
// 16 rows per block, 256 threads. ACT: 0 = none, 1 = silu
template <int ACT>
__global__ void gemm_nt(const float* __restrict__ in, const float* __restrict__ W,
                        const float* __restrict__ bias, float* __restrict__ out) {
    __shared__ float sW[64 * 64];   // transposed: sW[k*64+c] = W[c][k]
    __shared__ float sIn[16 * 64];
    int tid = threadIdx.x;
    for (int i = tid; i < 4096; i += 256) {
        int c = i >> 6, k = i & 63;
        sW[k * 64 + c] = W[i];
    }
    int row0 = blockIdx.x * 16;
    for (int i = tid; i < 1024; i += 256)
        sIn[i] = in[row0 * 64 + i];
    __syncthreads();

    int c = tid & 63;
    int r = tid >> 6;   // 0..3 -> rows r, r+4, r+8, r+12
    float a0 = 0.f, a1 = 0.f, a2 = 0.f, a3 = 0.f;
#pragma unroll
    for (int k = 0; k < 64; k++) {
        float w = sW[k * 64 + c];
        a0 += sIn[(r + 0) * 64 + k] * w;
        a1 += sIn[(r + 4) * 64 + k] * w;
        a2 += sIn[(r + 8) * 64 + k] * w;
        a3 += sIn[(r + 12) * 64 + k] * w;
    }
    float b = bias ? bias[c] : 0.f;
    a0 += b; a1 += b; a2 += b; a3 += b;
    if (ACT == 1) {   // silu
        a0 *= 1.f / (1.f + __expf(-a0));
        a1 *= 1.f / (1.f + __expf(-a1));
        a2 *= 1.f / (1.f + __expf(-a2));
        a3 *= 1.f / (1.f + __expf(-a3));
    }
    out[(row0 + r + 0) * 64 + c]  = a0;
    out[(row0 + r + 4) * 64 + c]  = a1;
    out[(row0 + r + 8) * 64 + c]  = a2;
    out[(row0 + r + 12) * 64 + c] = a3;
}

// ---------------- per-node attention scalars: a_s, a_d (warp per node) ----------------
__global__ void attn_scalars(const float* __restrict__ h2, const float* __restrict__ asw,
                             const float* __restrict__ adw) {
    int gtid = blockIdx.x * blockDim.x + threadIdx.x;
    int warp = gtid >> 5, lane = gtid & 31;
    if (warp >= NN) return;
    float x0 = h2[warp * 64 + lane];
    float x1 = h2[warp * 64 + 32 + lane];
    float s = x0 * asw[lane] + x1 * asw[32 + lane];
    float d = x0 * adw[lane] + x1 * adw[32 + lane];
#pragma unroll
    for (int o = 16; o; o >>= 1) {
        s += __shfl_down_sync(0xffffffffu, s, o);
        d += __shfl_down_sync(0xffffffffu, d, o);
    }
    if (lane == 0) {
        g_as[warp] = s;
        g_ad[warp] = d;
    }
}

// ---------------- per-layer prep: zero hout / denom, emax=-inf (and pool) ----------------
template <bool POOL>
__global__ void prep(float* __restrict__ hout) {
    int i = blockIdx.x * blockDim.x + threadIdx.x;
    if (i < NN * DD) hout[i] = 0.f;
    if (i < NN) {
        g_emax[i] = -INFINITY;
        g_denom[i] = 0.f;
    }
    if (POOL && i < NGR * DD) g_pool[i] = 0.f;
}

// ---------------- edge pass 1: e + segment max ----------------
__global__ void edge_max(const int* __restrict__ ei_a, const int* __restrict__ ei_b) {
    int t = blockIdx.x * blockDim.x + threadIdx.x;
    if (t >= E_TOT) return;
    int s, d;
    edge_sd(t, ei_a, ei_b, s, d);
    float e = g_as[s] + g_ad[d];
    e = (e > 0.f) ? e : GAT_SLOPE * e;
    g_e[t] = e;
    atomicMaxF(&g_emax[d], e);
}

// ---------------- edge pass 2: exp, denom, weighted scatter (warp per edge) ----------------
__global__ void edge_agg(const int* __restrict__ ei_a, const int* __restrict__ ei_b,
                         const float* __restrict__ h2, float* __restrict__ hout) {
    int gtid = blockIdx.x * blockDim.x + threadIdx.x;
    int warp = gtid >> 5, lane = gtid & 31;
    if (warp >= E_TOT) return;
    int s, d;
    edge_sd(warp, ei_a, ei_b, s, d);
    float ex = __expf(g_e[warp] - g_emax[d]);
    if (lane == 0) atomicAdd(&g_denom[d], ex);
    float v0 = ex * h2[s * 64 + lane];
    float v1 = ex * h2[s * 64 + 32 + lane];
    atomicAdd(&hout[d * 64 + lane], v0);
    atomicAdd(&hout[d * 64 + 32 + lane], v1);
}

// ---------------- finalize: /= denom, +bias, relu, (pool) ----------------
template <bool RELU, bool POOL>
__global__ void finalize(float* __restrict__ hout, const float* __restrict__ bias,
                         const int* __restrict__ batch) {
    int i = blockIdx.x * blockDim.x + threadIdx.x;
    if (i >= NN * DD) return;
    int node = i >> 6, c = i & 63;
    float v = hout[i] / g_denom[node] + bias[c];
    if (RELU) v = fmaxf(v, 0.f);
    hout[i] = v;
    if (POOL) atomicAdd(&g_pool[batch[node] * 64 + c], v);
}

// ---------------- FC head: one block per graph, 64 threads ----------------
__global__ void fc_head(const float* __restrict__ fc1w, const float* __restrict__ fc1b,
                        const float* __restrict__ bn1g, const float* __restrict__ bn1b,
                        const float* __restrict__ fc2w, const float* __restrict__ fc2b,
                        const float* __restrict__ bn2g, const float* __restrict__ bn2b,
                        const float* __restrict__ fc3w, const float* __restrict__ fc3b,
                        float* __restrict__ out) {
    __shared__ float sg[64];
    __shared__ float s1[64];
    __shared__ float red[2];
    int g = blockIdx.x, c = threadIdx.x;
    float inv = rsqrtf(1.0f + 1e-5f);

    sg[c] = g_pool[g * 64 + c];
    __syncthreads();

    float acc = fc1b[c];
#pragma unroll
    for (int k = 0; k < 64; k++) acc += sg[k] * fc1w[c * 64 + k];
    acc = (acc > 0.f) ? acc : FC_SLOPE * acc;
    acc = acc * inv * bn1g[c] + bn1b[c];
    s1[c] = acc;
    __syncthreads();

    float acc2 = fc2b[c];
#pragma unroll
    for (int k = 0; k < 64; k++) acc2 += s1[k] * fc2w[c * 64 + k];
    acc2 = (acc2 > 0.f) ? acc2 : FC_SLOPE * acc2;
    acc2 = acc2 * inv * bn2g[c] + bn2b[c];

    float p = acc2 * fc3w[c];
#pragma unroll
    for (int o = 16; o; o >>= 1) p += __shfl_down_sync(0xffffffffu, p, o);
    if ((c & 31) == 0) red[c >> 5] = p;
    __syncthreads();
    if (c == 0) out[g] = red[0] + red[1] + fc3b[0];
}

// ---------------- host-side layer driver ----------------
static void gat_layer(const float* hin, float* h2, float* hout,
                      const float* W, const float* asw, const float* adw, const float* bias,
                      const int* ei_a, const int* ei_b, const int* batch,
                      bool relu, bool pool) {
    gemm_nt<0><<<NN / 16, 256>>>(hin, W, nullptr, h2);
    attn_scalars<<<(NN * 32 + 255) / 256, 256>>>(h2, asw, adw);
    if (pool) prep<true><<<(NN * DD + 255) / 256, 256>>>(hout);
    else      prep<false><<<(NN * DD + 255) / 256, 256>>>(hout);
    edge_max<<<(E_TOT + 255) / 256, 256>>>(ei_a, ei_b);
    edge_agg<<<(E_TOT * 32 + 255) / 256, 256>>>(ei_a, ei_b, h2, hout);
    if (relu)      finalize<true, false><<<(NN * DD + 255) / 256, 256>>>(hout, bias, batch);
    else if (pool) finalize<false, true><<<(NN * DD + 255) / 256, 256>>>(hout, bias, batch);
    else           finalize<false, false><<<(NN * DD + 255) / 256, 256>>>(hout, bias, batch);
}

extern "C" void kernel_launch(void* const* d_in, const int* in_sizes, int n_in,
                              void* d_out, int out_size) {
    const float* x     = (const float*)d_in[0];
    const int*   ei_a  = (const int*)d_in[1];
    const int*   ei_b  = (const int*)d_in[2];
    const int*   batch = (const int*)d_in[3];
    const float* lin1_w = (const float*)d_in[4];
    const float* lin1_b = (const float*)d_in[5];
    const float* g1w = (const float*)d_in[6];
    const float* g1s = (const float*)d_in[7];
    const float* g1d = (const float*)d_in[8];
    const float* g1b = (const float*)d_in[9];
    const float* g2w = (const float*)d_in[10];
    const float* g2s = (const float*)d_in[11];
    const float* g2d = (const float*)d_in[12];
    const float* g2b = (const float*)d_in[13];
    const float* g3w = (const float*)d_in[14];
    const float* g3s = (const float*)d_in[15];
    const float* g3d = (const float*)d_in[16];
    const float* g3b = (const float*)d_in[17];
    const float* fc1w = (const float*)d_in[18];
    const float* fc1b = (const float*)d_in[19];
    const float* bn1g = (const float*)d_in[20];
    const float* bn1b = (const float*)d_in[21];
    const float* fc2w = (const float*)d_in[22];
    const float* fc2b = (const float*)d_in[23];
    const float* bn2g = (const float*)d_in[24];
    const float* bn2b = (const float*)d_in[25];
    const float* fc3w = (const float*)d_in[26];
    const float* fc3b = (const float*)d_in[27];
    float* out = (float*)d_out;

    float *A, *B, *C;
    cudaGetSymbolAddress((void**)&A, g_bufA);
    cudaGetSymbolAddress((void**)&B, g_bufB);
    cudaGetSymbolAddress((void**)&C, g_bufC);

    // lin1 + silu
    gemm_nt<1><<<NN / 16, 256>>>(x, lin1_w, lin1_b, A);

    // three GAT layers
    gat_layer(A, B, C, g1w, g1s, g1d, g1b, ei_a, ei_b, batch, true,  false);
    gat_layer(C, B, A, g2w, g2s, g2d, g2b, ei_a, ei_b, batch, true,  false);
    gat_layer(A, B, C, g3w, g3s, g3d, g3b, ei_a, ei_b, batch, false, true);

    // FC head
    fc_head<<<NGR, 64>>>(fc1w, fc1b, bn1g, bn1b, fc2w, fc2b, bn2g, bn2b, fc3w, fc3b, out);
}

// round 2
// speedup vs baseline: 1.0003x; 1.0003x over previous
#include <cuda_runtime.h>
#include <math.h>

#define NN      100000
#define DD      64
#define E_INTRA 1200000
#define E_INTER 400000
#define E_TOT   (E_INTRA + E_INTER + NN)   // 1,700,000 (self loops appended)
#define NGR     256
#define GAT_SLOPE 0.2f
#define FC_SLOPE  0.01f

// ---------------- static scratch (no allocations allowed) ----------------
__device__ float g_bufA[NN * DD];
__device__ float g_bufB[NN * DD];   // h2 = hin @ W^T
__device__ float g_bufC[NN * DD];
__device__ float g_e[E_TOT];
__device__ float g_as[NN];
__device__ float g_ad[NN];
__device__ float g_emax[NN];
__device__ float g_denom[NN];
__device__ float g_pool[NGR * DD];

// ---------------- helpers ----------------
__device__ __forceinline__ void edge_sd(int t, const int* __restrict__ ei_a,
                                        const int* __restrict__ ei_b, int& s, int& d) {
    if (t < E_INTRA) {
        s = ei_a[t];
        d = ei_a[E_INTRA + t];
    } else if (t < E_INTRA + E_INTER) {
        int u = t - E_INTRA;
        s = ei_b[u];
        d = ei_b[E_INTER + u];
    } else {
        s = d = t - (E_INTRA + E_INTER);
    }
}

__device__ __forceinline__ void atomicMaxF(float* addr, float v) {
    int old = __float_as_int(*addr);
    while (__int_as_float(old) < v) {
        int assumed = old;
        old = atomicCAS((int*)addr, assumed, __float_as_int(v));
        if (old == assumed) break;
    }
}

// ---------------- GEMM: out = act(in @ W^T [+ bias]) ----------------
// in [NN,64], W [64,64] row-major (out[i][c] = sum_k in[i][k]*W[c][k])
// 16 rows per block, 256 threads. ACT: 0 = none, 1 = silu
template <int ACT>
__global__ void gemm_nt(const float* __restrict__ in, const float* __restrict__ W,
                        const float* __restrict__ bias, float* __restrict__ out) {
    __shared__ float sW[64 * 64];   // transposed: sW[k*64+c] = W[c][k]
    __shared__ float sIn[16 * 64];
    int tid = threadIdx.x;
    for (int i = tid; i < 4096; i += 256) {
        int c = i >> 6, k = i & 63;
        sW[k * 64 + c] = W[i];
    }
    int row0 = blockIdx.x * 16;
    for (int i = tid; i < 1024; i += 256)
        sIn[i] = in[row0 * 64 + i];
    __syncthreads();

    int c = tid & 63;
    int r = tid >> 6;   // 0..3 -> rows r, r+4, r+8, r+12
    float a0 = 0.f, a1 = 0.f, a2 = 0.f, a3 = 0.f;
#pragma unroll
    for (int k = 0; k < 64; k++) {
        float w = sW[k * 64 + c];
        a0 += sIn[(r + 0) * 64 + k] * w;
        a1 += sIn[(r + 4) * 64 + k] * w;
        a2 += sIn[(r + 8) * 64 + k] * w;
        a3 += sIn[(r + 12) * 64 + k] * w;
    }
    float b = bias ? bias[c] : 0.f;
    a0 += b; a1 += b; a2 += b; a3 += b;
    if (ACT == 1) {   // silu
        a0 *= 1.f / (1.f + __expf(-a0));
        a1 *= 1.f / (1.f + __expf(-a1));
        a2 *= 1.f / (1.f + __expf(-a2));
        a3 *= 1.f / (1.f + __expf(-a3));
    }
    out[(row0 + r + 0) * 64 + c]  = a0;
    out[(row0 + r + 4) * 64 + c]  = a1;
    out[(row0 + r + 8) * 64 + c]  = a2;
    out[(row0 + r + 12) * 64 + c] = a3;
}

// ---------------- per-node attention scalars: a_s, a_d (warp per node) ----------------
__global__ void attn_scalars(const float* __restrict__ h2, const float* __restrict__ asw,
                             const float* __restrict__ adw) {
    int gtid = blockIdx.x * blockDim.x + threadIdx.x;
    int warp = gtid >> 5, lane = gtid & 31;
    if (warp >= NN) return;
    float x0 = h2[warp * 64 + lane];
    float x1 = h2[warp * 64 + 32 + lane];
    float s = x0 * asw[lane] + x1 * asw[32 + lane];
    float d = x0 * adw[lane] + x1 * adw[32 + lane];
#pragma unroll
    for (int o = 16; o; o >>= 1) {
        s += __shfl_down_sync(0xffffffffu, s, o);
        d += __shfl_down_sync(0xffffffffu, d, o);
    }
    if (lane == 0) {
        g_as[warp] = s;
        g_ad[warp] = d;
    }
}

// ---------------- per-layer prep: zero hout / denom, emax=-inf (and pool) ----------------
template <bool POOL>
__global__ void prep(float* __restrict__ hout) {
    int i = blockIdx.x * blockDim.x + threadIdx.x;
    if (i < NN * DD) hout[i] = 0.f;
    if (i < NN) {
        g_emax[i] = -INFINITY;
        g_denom[i] = 0.f;
    }
    if (POOL && i < NGR * DD) g_pool[i] = 0.f;
}

// ---------------- edge pass 1: e + segment max ----------------
__global__ void edge_max(const int* __restrict__ ei_a, const int* __restrict__ ei_b) {
    int t = blockIdx.x * blockDim.x + threadIdx.x;
    if (t >= E_TOT) return;
    int s, d;
    edge_sd(t, ei_a, ei_b, s, d);
    float e = g_as[s] + g_ad[d];
    e = (e > 0.f) ? e : GAT_SLOPE * e;
    g_e[t] = e;
    atomicMaxF(&g_emax[d], e);
}

// ---------------- edge pass 2: exp, denom, weighted scatter (warp per edge) ----------------
__global__ void edge_agg(const int* __restrict__ ei_a, const int* __restrict__ ei_b,
                         const float* __restrict__ h2, float* __restrict__ hout) {
    int gtid = blockIdx.x * blockDim.x + threadIdx.x;
    int warp = gtid >> 5, lane = gtid & 31;
    if (warp >= E_TOT) return;
    int s, d;
    edge_sd(warp, ei_a, ei_b, s, d);
    float ex = __expf(g_e[warp] - g_emax[d]);
    if (lane == 0) atomicAdd(&g_denom[d], ex);
    float v0 = ex * h2[s * 64 + lane];
    float v1 = ex * h2[s * 64 + 32 + lane];
    atomicAdd(&hout[d * 64 + lane], v0);
    atomicAdd(&hout[d * 64 + 32 + lane], v1);
}

// ---------------- finalize: /= denom, +bias, relu, (pool) ----------------
template <bool RELU, bool POOL>
__global__ void finalize(float* __restrict__ hout, const float* __restrict__ bias,
                         const int* __restrict__ batch) {
    int i = blockIdx.x * blockDim.x + threadIdx.x;
    if (i >= NN * DD) return;
    int node = i >> 6, c = i & 63;
    float v = hout[i] / g_denom[node] + bias[c];
    if (RELU) v = fmaxf(v, 0.f);
    hout[i] = v;
    if (POOL) atomicAdd(&g_pool[batch[node] * 64 + c], v);
}

// ---------------- FC head: one block per graph, 64 threads ----------------
__global__ void fc_head(const float* __restrict__ fc1w, const float* __restrict__ fc1b,
                        const float* __restrict__ bn1g, const float* __restrict__ bn1b,
                        const float* __restrict__ fc2w, const float* __restrict__ fc2b,
                        const float* __restrict__ bn2g, const float* __restrict__ bn2b,
                        const float* __restrict__ fc3w, const float* __restrict__ fc3b,
                        float* __restrict__ out) {
    __shared__ float sg[64];
    __shared__ float s1[64];
    __shared__ float red[2];
    int g = blockIdx.x, c = threadIdx.x;
    float inv = rsqrtf(1.0f + 1e-5f);

    sg[c] = g_pool[g * 64 + c];
    __syncthreads();

    float acc = fc1b[c];
#pragma unroll
    for (int k = 0; k < 64; k++) acc += sg[k] * fc1w[c * 64 + k];
    acc = (acc > 0.f) ? acc : FC_SLOPE * acc;
    acc = acc * inv * bn1g[c] + bn1b[c];
    s1[c] = acc;
    __syncthreads();

    float acc2 = fc2b[c];
#pragma unroll
    for (int k = 0; k < 64; k++) acc2 += s1[k] * fc2w[c * 64 + k];
    acc2 = (acc2 > 0.f) ? acc2 : FC_SLOPE * acc2;
    acc2 = acc2 * inv * bn2g[c] + bn2b[c];

    float p = acc2 * fc3w[c];
#pragma unroll
    for (int o = 16; o; o >>= 1) p += __shfl_down_sync(0xffffffffu, p, o);
    if ((c & 31) == 0) red[c >> 5] = p;
    __syncthreads();
    if (c == 0) out[g] = red[0] + red[1] + fc3b[0];
}

// ---------------- host-side layer driver ----------------
static void gat_layer(const float* hin, float* h2, float* hout,
                      const float* W, const float* asw, const float* adw, const float* bias,
                      const int* ei_a, const int* ei_b, const int* batch,
                      bool relu, bool pool) {
    gemm_nt<0><<<NN / 16, 256>>>(hin, W, nullptr, h2);
    attn_scalars<<<(NN * 32 + 255) / 256, 256>>>(h2, asw, adw);
    if (pool) prep<true><<<(NN * DD + 255) / 256, 256>>>(hout);
    else      prep<false><<<(NN * DD + 255) / 256, 256>>>(hout);
    edge_max<<<(E_TOT + 255) / 256, 256>>>(ei_a, ei_b);
    edge_agg<<<(E_TOT * 32 + 255) / 256, 256>>>(ei_a, ei_b, h2, hout);
    if (relu)      finalize<true, false><<<(NN * DD + 255) / 256, 256>>>(hout, bias, batch);
    else if (pool) finalize<false, true><<<(NN * DD + 255) / 256, 256>>>(hout, bias, batch);
    else           finalize<false, false><<<(NN * DD + 255) / 256, 256>>>(hout, bias, batch);
}

extern "C" void kernel_launch(void* const* d_in, const int* in_sizes, int n_in,
                              void* d_out, int out_size) {
    const float* x     = (const float*)d_in[0];
    const int*   ei_a  = (const int*)d_in[1];
    const int*   ei_b  = (const int*)d_in[2];
    const int*   batch = (const int*)d_in[3];
    const float* lin1_w = (const float*)d_in[4];
    const float* lin1_b = (const float*)d_in[5];
    const float* g1w = (const float*)d_in[6];
    const float* g1s = (const float*)d_in[7];
    const float* g1d = (const float*)d_in[8];
    const float* g1b = (const float*)d_in[9];
    const float* g2w = (const float*)d_in[10];
    const float* g2s = (const float*)d_in[11];
    const float* g2d = (const float*)d_in[12];
    const float* g2b = (const float*)d_in[13];
    const float* g3w = (const float*)d_in[14];
    const float* g3s = (const float*)d_in[15];
    const float* g3d = (const float*)d_in[16];
    const float* g3b = (const float*)d_in[17];
    const float* fc1w = (const float*)d_in[18];
    const float* fc1b = (const float*)d_in[19];
    const float* bn1g = (const float*)d_in[20];
    const float* bn1b = (const float*)d_in[21];
    const float* fc2w = (const float*)d_in[22];
    const float* fc2b = (const float*)d_in[23];
    const float* bn2g = (const float*)d_in[24];
    const float* bn2b = (const float*)d_in[25];
    const float* fc3w = (const float*)d_in[26];
    const float* fc3b = (const float*)d_in[27];
    float* out = (float*)d_out;

    float *A, *B, *C;
    cudaGetSymbolAddress((void**)&A, g_bufA);
    cudaGetSymbolAddress((void**)&B, g_bufB);
    cudaGetSymbolAddress((void**)&C, g_bufC);

    // lin1 + silu
    gemm_nt<1><<<NN / 16, 256>>>(x, lin1_w, lin1_b, A);

    // three GAT layers
    gat_layer(A, B, C, g1w, g1s, g1d, g1b, ei_a, ei_b, batch, true,  false);
    gat_layer(C, B, A, g2w, g2s, g2d, g2b, ei_a, ei_b, batch, true,  false);
    gat_layer(A, B, C, g3w, g3s, g3d, g3b, ei_a, ei_b, batch, false, true);

    // FC head
    fc_head<<<NGR, 64>>>(fc1w, fc1b, bn1g, bn1b, fc2w, fc2b, bn2g, bn2b, fc3w, fc3b, out);
}

// round 3
// speedup vs baseline: 1.0014x; 1.0011x over previous
#include <cuda_runtime.h>
#include <math.h>

#define NN      100000
#define DD      64
#define E_INTRA 1200000
#define E_INTER 400000
#define E_TOT   (E_INTRA + E_INTER + NN)   // 1,700,000 (self loops appended)
#define NGR     256
#define GAT_SLOPE 0.2f
#define FC_SLOPE  0.01f

// ---------------- static scratch (no allocations allowed) ----------------
__device__ float g_bufA[NN * DD];
__device__ float g_bufB[NN * DD];   // h2 = hin @ W^T
__device__ float g_bufC[NN * DD];
__device__ float g_e[E_TOT];
__device__ float g_as[NN];
__device__ float g_ad[NN];
__device__ float g_emax[NN];
__device__ float g_denom[NN];
__device__ float g_pool[NGR * DD];

// ---------------- helpers ----------------
__device__ __forceinline__ void edge_sd(int t, const int* __restrict__ ei_a,
                                        const int* __restrict__ ei_b, int& s, int& d) {
    if (t < E_INTRA) {
        s = ei_a[t];
        d = ei_a[E_INTRA + t];
    } else if (t < E_INTRA + E_INTER) {
        int u = t - E_INTRA;
        s = ei_b[u];
        d = ei_b[E_INTER + u];
    } else {
        s = d = t - (E_INTRA + E_INTER);
    }
}

__device__ __forceinline__ void atomicMaxF(float* addr, float v) {
    int old = __float_as_int(*addr);
    while (__int_as_float(old) < v) {
        int assumed = old;
        old = atomicCAS((int*)addr, assumed, __float_as_int(v));
        if (old == assumed) break;
    }
}

// ---------------- GEMM: out = act(in @ W^T [+ bias]) ----------------
// in [NN,64], W [64,64] row-major (out[i][c] = sum_k in[i][k]*W[c][k])
// 16 rows per block, 256 threads. ACT: 0 = none, 1 = silu
template <int ACT>
__global__ void gemm_nt(const float* __restrict__ in, const float* __restrict__ W,
                        const float* __restrict__ bias, float* __restrict__ out) {
    __shared__ float sW[64 * 64];   // transposed: sW[k*64+c] = W[c][k]
    __shared__ float sIn[16 * 64];
    int tid = threadIdx.x;
    for (int i = tid; i < 4096; i += 256) {
        int c = i >> 6, k = i & 63;
        sW[k * 64 + c] = W[i];
    }
    int row0 = blockIdx.x * 16;
    for (int i = tid; i < 1024; i += 256)
        sIn[i] = in[row0 * 64 + i];
    __syncthreads();

    int c = tid & 63;
    int r = tid >> 6;   // 0..3 -> rows r, r+4, r+8, r+12
    float a0 = 0.f, a1 = 0.f, a2 = 0.f, a3 = 0.f;
#pragma unroll
    for (int k = 0; k < 64; k++) {
        float w = sW[k * 64 + c];
        a0 += sIn[(r + 0) * 64 + k] * w;
        a1 += sIn[(r + 4) * 64 + k] * w;
        a2 += sIn[(r + 8) * 64 + k] * w;
        a3 += sIn[(r + 12) * 64 + k] * w;
    }
    float b = bias ? bias[c] : 0.f;
    a0 += b; a1 += b; a2 += b; a3 += b;
    if (ACT == 1) {   // silu
        a0 *= 1.f / (1.f + __expf(-a0));
        a1 *= 1.f / (1.f + __expf(-a1));
        a2 *= 1.f / (1.f + __expf(-a2));
        a3 *= 1.f / (1.f + __expf(-a3));
    }
    out[(row0 + r + 0) * 64 + c]  = a0;
    out[(row0 + r + 4) * 64 + c]  = a1;
    out[(row0 + r + 8) * 64 + c]  = a2;
    out[(row0 + r + 12) * 64 + c] = a3;
}

// ---------------- per-node attention scalars: a_s, a_d (warp per node) ----------------
__global__ void attn_scalars(const float* __restrict__ h2, const float* __restrict__ asw,
                             const float* __restrict__ adw) {
    int gtid = blockIdx.x * blockDim.x + threadIdx.x;
    int warp = gtid >> 5, lane = gtid & 31;
    if (warp >= NN) return;
    float x0 = h2[warp * 64 + lane];
    float x1 = h2[warp * 64 + 32 + lane];
    float s = x0 * asw[lane] + x1 * asw[32 + lane];
    float d = x0 * adw[lane] + x1 * adw[32 + lane];
#pragma unroll
    for (int o = 16; o; o >>= 1) {
        s += __shfl_down_sync(0xffffffffu, s, o);
        d += __shfl_down_sync(0xffffffffu, d, o);
    }
    if (lane == 0) {
        g_as[warp] = s;
        g_ad[warp] = d;
    }
}

// ---------------- per-layer prep: zero hout / denom, emax=-inf (and pool) ----------------
template <bool POOL>
__global__ void prep(float* __restrict__ hout) {
    int i = blockIdx.x * blockDim.x + threadIdx.x;
    if (i < NN * DD) hout[i] = 0.f;
    if (i < NN) {
        g_emax[i] = -INFINITY;
        g_denom[i] = 0.f;
    }
    if (POOL && i < NGR * DD) g_pool[i] = 0.f;
}

// ---------------- edge pass 1: e + segment max ----------------
__global__ void edge_max(const int* __restrict__ ei_a, const int* __restrict__ ei_b) {
    int t = blockIdx.x * blockDim.x + threadIdx.x;
    if (t >= E_TOT) return;
    int s, d;
    edge_sd(t, ei_a, ei_b, s, d);
    float e = g_as[s] + g_ad[d];
    e = (e > 0.f) ? e : GAT_SLOPE * e;
    g_e[t] = e;
    atomicMaxF(&g_emax[d], e);
}

// ---------------- edge pass 2: exp, denom, weighted scatter (warp per edge) ----------------
__global__ void edge_agg(const int* __restrict__ ei_a, const int* __restrict__ ei_b,
                         const float* __restrict__ h2, float* __restrict__ hout) {
    int gtid = blockIdx.x * blockDim.x + threadIdx.x;
    int warp = gtid >> 5, lane = gtid & 31;
    if (warp >= E_TOT) return;
    int s, d;
    edge_sd(warp, ei_a, ei_b, s, d);
    float ex = __expf(g_e[warp] - g_emax[d]);
    if (lane == 0) atomicAdd(&g_denom[d], ex);
    float v0 = ex * h2[s * 64 + lane];
    float v1 = ex * h2[s * 64 + 32 + lane];
    atomicAdd(&hout[d * 64 + lane], v0);
    atomicAdd(&hout[d * 64 + 32 + lane], v1);
}

// ---------------- finalize: /= denom, +bias, relu, (pool) ----------------
template <bool RELU, bool POOL>
__global__ void finalize(float* __restrict__ hout, const float* __restrict__ bias,
                         const int* __restrict__ batch) {
    int i = blockIdx.x * blockDim.x + threadIdx.x;
    if (i >= NN * DD) return;
    int node = i >> 6, c = i & 63;
    float v = hout[i] / g_denom[node] + bias[c];
    if (RELU) v = fmaxf(v, 0.f);
    hout[i] = v;
    if (POOL) atomicAdd(&g_pool[batch[node] * 64 + c], v);
}

// ---------------- FC head: one block per graph, 64 threads ----------------
__global__ void fc_head(const float* __restrict__ fc1w, const float* __restrict__ fc1b,
                        const float* __restrict__ bn1g, const float* __restrict__ bn1b,
                        const float* __restrict__ fc2w, const float* __restrict__ fc2b,
                        const float* __restrict__ bn2g, const float* __restrict__ bn2b,
                        const float* __restrict__ fc3w, const float* __restrict__ fc3b,
                        float* __restrict__ out) {
    __shared__ float sg[64];
    __shared__ float s1[64];
    __shared__ float red[2];
    int g = blockIdx.x, c = threadIdx.x;
    float inv = rsqrtf(1.0f + 1e-5f);

    sg[c] = g_pool[g * 64 + c];
    __syncthreads();

    float acc = fc1b[c];
#pragma unroll
    for (int k = 0; k < 64; k++) acc += sg[k] * fc1w[c * 64 + k];
    acc = (acc > 0.f) ? acc : FC_SLOPE * acc;
    acc = acc * inv * bn1g[c] + bn1b[c];
    s1[c] = acc;
    __syncthreads();

    float acc2 = fc2b[c];
#pragma unroll
    for (int k = 0; k < 64; k++) acc2 += s1[k] * fc2w[c * 64 + k];
    acc2 = (acc2 > 0.f) ? acc2 : FC_SLOPE * acc2;
    acc2 = acc2 * inv * bn2g[c] + bn2b[c];

    float p = acc2 * fc3w[c];
#pragma unroll
    for (int o = 16; o; o >>= 1) p += __shfl_down_sync(0xffffffffu, p, o);
    if ((c & 31) == 0) red[c >> 5] = p;
    __syncthreads();
    if (c == 0) out[g] = red[0] + red[1] + fc3b[0];
}

// ---------------- host-side layer driver ----------------
static void gat_layer(const float* hin, float* h2, float* hout,
                      const float* W, const float* asw, const float* adw, const float* bias,
                      const int* ei_a, const int* ei_b, const int* batch,
                      bool relu, bool pool) {
    gemm_nt<0><<<NN / 16, 256>>>(hin, W, nullptr, h2);
    attn_scalars<<<(NN * 32 + 255) / 256, 256>>>(h2, asw, adw);
    if (pool) prep<true><<<(NN * DD + 255) / 256, 256>>>(hout);
    else      prep<false><<<(NN * DD + 255) / 256, 256>>>(hout);
    edge_max<<<(E_TOT + 255) / 256, 256>>>(ei_a, ei_b);
    edge_agg<<<(E_TOT * 32 + 255) / 256, 256>>>(ei_a, ei_b, h2, hout);
    if (relu)      finalize<true, false><<<(NN * DD + 255) / 256, 256>>>(hout, bias, batch);
    else if (pool) finalize<false, true><<<(NN * DD + 255) / 256, 256>>>(hout, bias, batch);
    else           finalize<false, false><<<(NN * DD + 255) / 256, 256>>>(hout, bias, batch);
}

extern "C" void kernel_launch(void* const* d_in, const int* in_sizes, int n_in,
                              void* d_out, int out_size) {
    const float* x     = (const float*)d_in[0];
    const int*   ei_a  = (const int*)d_in[1];
    const int*   ei_b  = (const int*)d_in[2];
    const int*   batch = (const int*)d_in[3];
    const float* lin1_w = (const float*)d_in[4];
    const float* lin1_b = (const float*)d_in[5];
    const float* g1w = (const float*)d_in[6];
    const float* g1s = (const float*)d_in[7];
    const float* g1d = (const float*)d_in[8];
    const float* g1b = (const float*)d_in[9];
    const float* g2w = (const float*)d_in[10];
    const float* g2s = (const float*)d_in[11];
    const float* g2d = (const float*)d_in[12];
    const float* g2b = (const float*)d_in[13];
    const float* g3w = (const float*)d_in[14];
    const float* g3s = (const float*)d_in[15];
    const float* g3d = (const float*)d_in[16];
    const float* g3b = (const float*)d_in[17];
    const float* fc1w = (const float*)d_in[18];
    const float* fc1b = (const float*)d_in[19];
    const float* bn1g = (const float*)d_in[20];
    const float* bn1b = (const float*)d_in[21];
    const float* fc2w = (const float*)d_in[22];
    const float* fc2b = (const float*)d_in[23];
    const float* bn2g = (const float*)d_in[24];
    const float* bn2b = (const float*)d_in[25];
    const float* fc3w = (const float*)d_in[26];
    const float* fc3b = (const float*)d_in[27];
    float* out = (float*)d_out;

    float *A, *B, *C;
    cudaGetSymbolAddress((void**)&A, g_bufA);
    cudaGetSymbolAddress((void**)&B, g_bufB);
    cudaGetSymbolAddress((void**)&C, g_bufC);

    // lin1 + silu
    gemm_nt<1><<<NN / 16, 256>>>(x, lin1_w, lin1_b, A);

    // three GAT layers
    gat_layer(A, B, C, g1w, g1s, g1d, g1b, ei_a, ei_b, batch, true,  false);
    gat_layer(C, B, A, g2w, g2s, g2d, g2b, ei_a, ei_b, batch, true,  false);
    gat_layer(A, B, C, g3w, g3s, g3d, g3b, ei_a, ei_b, batch, false, true);

    // FC head
    fc_head<<<NGR, 64>>>(fc1w, fc1b, bn1g, bn1b, fc2w, fc2b, bn2g, bn2b, fc3w, fc3b, out);
}